// round 6
// baseline (speedup 1.0000x reference)
#include <cuda_runtime.h>
#include <cstdint>
#include <math.h>

#define SEQ 2048
#define EMB 1024
#define NBQ 256
#define NH 16
#define HD 64
#define NBATCH 2
#define NROWS (NBATCH*SEQ)   // 4096
#define NKT (SEQ/64)         // 32 kv tiles
#define NQT (SEQ/128)        // 16 q tiles

// ---------------- scratch (device globals) ---------------------------------
__device__ float g_Wq[EMB*EMB];
__device__ float g_Wk[EMB*EMB];
__device__ float g_Wv[EMB*EMB];
__device__ float g_Wo[EMB*EMB];
__device__ float g_xr[NROWS*EMB];
__device__ float g_Q[NROWS*EMB];
__device__ float g_K[NROWS*EMB];     // head-dim interleaved within 8-groups
__device__ float g_V[NROWS*EMB];     // [b,h,d,s] transposed, s interleaved
__device__ float g_ctx[NROWS*EMB];
__device__ int   g_msum[NQT*NKT];

// ---------------- helpers ---------------------------------------------------
__device__ __forceinline__ unsigned f2tf32(float x) {
    unsigned u;
    asm("cvt.rna.tf32.f32 %0, %1;" : "=r"(u) : "f"(x));
    return u;
}
__device__ __forceinline__ float tf32f(float x) { return __uint_as_float(f2tf32(x)); }

// interleave within an 8-group: 0..3 -> 0,2,4,6 ; 4..7 -> 1,3,5,7
__device__ __forceinline__ int perm8(int c) {
    int c8 = c & 7;
    return (c & ~7) | ((c8 < 4) ? (2 * c8) : (2 * (c8 - 4) + 1));
}

__device__ __forceinline__ void mma_tf32(float* d, const unsigned* a, const unsigned* b) {
    asm volatile(
        "mma.sync.aligned.m16n8k8.row.col.f32.tf32.tf32.f32 "
        "{%0,%1,%2,%3},{%4,%5,%6,%7},{%8,%9},{%0,%1,%2,%3};"
        : "+f"(d[0]), "+f"(d[1]), "+f"(d[2]), "+f"(d[3])
        : "r"(a[0]), "r"(a[1]), "r"(a[2]), "r"(a[3]), "r"(b[0]), "r"(b[1]));
}

__device__ __forceinline__ uint32_t sa(const void* p) {
    return (uint32_t)__cvta_generic_to_shared(p);
}
__device__ __forceinline__ void cpa16(uint32_t s, const void* g) {
    asm volatile("cp.async.cg.shared.global [%0], [%1], 16;" :: "r"(s), "l"(g));
}
__device__ __forceinline__ void cp_commit() {
    asm volatile("cp.async.commit_group;" ::: "memory");
}
__device__ __forceinline__ void cp_wait0() {
    asm volatile("cp.async.wait_group 0;" ::: "memory");
}

// ---------------- x pre-round to tf32 ---------------------------------------
__global__ void round_kernel(const float* __restrict__ in, float* __restrict__ outp, int n4) {
    int i = blockIdx.x * blockDim.x + threadIdx.x;
    if (i >= n4) return;
    float4 v = ((const float4*)in)[i];
    v.x = tf32f(v.x); v.y = tf32f(v.y); v.z = tf32f(v.z); v.w = tf32f(v.w);
    ((float4*)outp)[i] = v;
}

// ---------------- weight expansion (quaternion left-mult), 4-in-1 ----------
struct Exp4 { const float* W[4]; float* Wb[4]; };

__global__ void expand4_kernel(Exp4 e) {
    int z = blockIdx.y;
    int idx = blockIdx.x * blockDim.x + threadIdx.x;
    if (idx >= NBQ * NBQ) return;
    int o = idx / NBQ;
    int n = idx % NBQ;
    const float* w = e.W[z] + (o * NBQ + n) * 4;
    float w0 = tf32f(w[0]), w1 = tf32f(w[1]), w2 = tf32f(w[2]), w3 = tf32f(w[3]);
    float* base = e.Wb[z] + (n * 4) * EMB + o * 4;
    *(float4*)(base + 0 * EMB) = make_float4( w0,  w1,  w2,  w3);
    *(float4*)(base + 1 * EMB) = make_float4(-w1,  w0,  w3, -w2);
    *(float4*)(base + 2 * EMB) = make_float4(-w2, -w3,  w0,  w1);
    *(float4*)(base + 3 * EMB) = make_float4(-w3,  w2, -w1,  w0);
}

// ---------------- mask tile summary (128q x 64k tiles) ----------------------
__global__ void mask_summary(const int* __restrict__ mask, int* __restrict__ sum) {
    int tile = blockIdx.x;
    int qt = tile / NKT, kt = tile % NKT;
    int tid = threadIdx.x;
    int ok = 1;
    for (int i = tid; i < 128*64; i += 256) {
        int r = i / 64, c = i % 64;
        ok &= (mask[(qt*128 + r) * SEQ + kt*64 + c] != 0);
    }
    int allok = __syncthreads_and(ok);
    if (tid == 0) sum[tile] = allok;
}

// ---------------- TF32 tensor-core GEMM (cp.async double-buffered) ----------
// All operands pre-rounded to tf32 in gmem -> raw-bit mma is exact.
#define ASTR 36
#define BSTR 136

struct GemmArgs {
    const float* A;
    const float* W[3];
    const float* bias[3];
    float* out[3];
    float oscale[3];
    int   mode[3];     // 0 = plain, 1 = K head-dim perm, 2 = V transpose+s-perm
    int   round_out;
};

__global__ __launch_bounds__(256) void gemm_tf32(GemmArgs ga) {
    extern __shared__ float gs[];
    float* Asm = gs;                       // 2 * 128*ASTR
    float* Bsm = gs + 2 * 128 * ASTR;      // 2 * 32*BSTR

    int tid = threadIdx.x;
    int z = blockIdx.z;
    const float* A = ga.A;
    const float* W = ga.W[z];
    const float* bias = ga.bias[z];
    float* C = ga.out[z];

    int bm = blockIdx.y * 128;
    int bn = blockIdx.x * 128;
    int warp = tid / 32, lane = tid % 32;
    int gid = lane >> 2, tig = lane & 3;
    int wm = (warp / 4) * 64, wn = (warp % 4) * 32;

    // cp.async thread mapping
    int ar = tid >> 1;             // A row 0..127
    int ac = (tid & 1) * 16;       // A col half (16 floats)
    int br = tid >> 3;             // B row 0..31
    int bc = (tid & 7) * 16;       // B col (16 floats)

    float acc[4][4][4];
#pragma unroll
    for (int mt = 0; mt < 4; mt++)
#pragma unroll
        for (int nt = 0; nt < 4; nt++)
#pragma unroll
            for (int r = 0; r < 4; r++) acc[mt][nt][r] = 0.0f;

#define GLOAD(kt, buf)                                                         \
    {                                                                          \
        const float* asrc = A + (long)(bm + ar) * EMB + (kt) * 32 + ac;        \
        uint32_t adst = sa(Asm + (buf) * 128 * ASTR + ar * ASTR + ac);         \
        _Pragma("unroll")                                                      \
        for (int j = 0; j < 4; j++) cpa16(adst + j * 16, asrc + j * 4);        \
        const float* bsrc = W + (long)((kt) * 32 + br) * EMB + bn + bc;        \
        uint32_t bdst = sa(Bsm + (buf) * 32 * BSTR + br * BSTR + bc);          \
        _Pragma("unroll")                                                      \
        for (int j = 0; j < 4; j++) cpa16(bdst + j * 16, bsrc + j * 4);        \
    }

    GLOAD(0, 0);
    cp_commit();
    cp_wait0();
    __syncthreads();

    for (int kt = 0; kt < EMB / 32; kt++) {
        if (kt + 1 < EMB / 32) {
            GLOAD(kt + 1, (kt + 1) & 1);
            cp_commit();
        }

        const float* As = Asm + (kt & 1) * 128 * ASTR;
        const float* Bs = Bsm + (kt & 1) * 32 * BSTR;
#pragma unroll
        for (int ks = 0; ks < 4; ks++) {
            int k0 = ks * 8;
            unsigned af[4][4], bf[4][2];
#pragma unroll
            for (int mt = 0; mt < 4; mt++) {
                int r0 = wm + mt * 16;
                af[mt][0] = __float_as_uint(As[(r0 + gid)     * ASTR + k0 + tig]);
                af[mt][1] = __float_as_uint(As[(r0 + gid + 8) * ASTR + k0 + tig]);
                af[mt][2] = __float_as_uint(As[(r0 + gid)     * ASTR + k0 + tig + 4]);
                af[mt][3] = __float_as_uint(As[(r0 + gid + 8) * ASTR + k0 + tig + 4]);
            }
#pragma unroll
            for (int nt = 0; nt < 4; nt++) {
                int c0 = wn + nt * 8;
                bf[nt][0] = __float_as_uint(Bs[(k0 + tig)     * BSTR + c0 + gid]);
                bf[nt][1] = __float_as_uint(Bs[(k0 + tig + 4) * BSTR + c0 + gid]);
            }
#pragma unroll
            for (int mt = 0; mt < 4; mt++)
#pragma unroll
                for (int nt = 0; nt < 4; nt++)
                    mma_tf32(acc[mt][nt], af[mt], bf[nt]);
        }
        if (kt + 1 < EMB / 32) {
            cp_wait0();
            __syncthreads();
        }
    }

    float os = ga.oscale[z];
    int rnd = ga.round_out;
    int mode = ga.mode[z];
#pragma unroll
    for (int mt = 0; mt < 4; mt++)
#pragma unroll
        for (int nt = 0; nt < 4; nt++) {
            int gm = bm + wm + mt * 16 + gid;
            int gn = bn + wn + nt * 8 + tig * 2;
            float b0 = bias[gn], b1 = bias[gn + 1];
            float v0 = (acc[mt][nt][0] + b0) * os;
            float v1 = (acc[mt][nt][1] + b1) * os;
            float v2 = (acc[mt][nt][2] + b0) * os;
            float v3 = (acc[mt][nt][3] + b1) * os;
            if (rnd) { v0 = tf32f(v0); v1 = tf32f(v1); v2 = tf32f(v2); v3 = tf32f(v3); }
            if (mode == 0) {
                *(float2*)(C + (long)gm * EMB + gn) = make_float2(v0, v1);
                *(float2*)(C + (long)(gm + 8) * EMB + gn) = make_float2(v2, v3);
            } else if (mode == 1) {
                // K: permute head-dim within 8-groups
                int p0 = perm8(gn), p1 = perm8(gn + 1);
                C[(long)gm * EMB + p0] = v0;
                C[(long)gm * EMB + p1] = v1;
                C[(long)(gm + 8) * EMB + p0] = v2;
                C[(long)(gm + 8) * EMB + p1] = v3;
            } else {
                // V: transpose to [b,h,d,s] with s interleaved within 8-groups
                int b0i = gm >> 11, s0 = gm & (SEQ - 1);
                int s0p = perm8(s0), s1p = perm8(s0 + 8);  // gm+8: same group base? (s0+8 crosses group)
                int h = gn >> 6, d = gn & 63;
                long base = ((long)(b0i * NH + h) * HD) * SEQ;
                C[base + (long)d * SEQ + s0p] = v0;
                C[base + (long)(d + 1) * SEQ + s0p] = v1;
                C[base + (long)d * SEQ + s1p] = v2;
                C[base + (long)(d + 1) * SEQ + s1p] = v3;
            }
        }
}

// ---------------- TF32 flash attention (BQ=128, vectorized frag loads) ------
#define BQ 128
#define BKV 64
#define QSTR 68
#define KSTR 68
#define VSTR 68

__global__ __launch_bounds__(256, 2) void flash_tf32(
    const float* __restrict__ Q, const float* __restrict__ K,
    const float* __restrict__ Vt, const int* __restrict__ mask,
    const int* __restrict__ msum, float* __restrict__ ctx)
{
    extern __shared__ float fs[];
    float* Qs = fs;                         // BQ*QSTR
    float* Ks = Qs + BQ * QSTR;             // 2*BKV*KSTR
    float* Vs = Ks + 2 * BKV * KSTR;        // 2*HD*VSTR (d-major)

    int tid = threadIdx.x;
    int w = tid / 32, lane = tid % 32;
    int gid = lane >> 2, tig = lane & 3;
    int qt = blockIdx.x, h = blockIdx.y, b = blockIdx.z;
    int q0 = qt * BQ;
    int bh = b * NH + h;

    // Q tile (already tf32-rounded + pre-scaled)
    {
        int row = tid >> 1;
        int c0 = (tid & 1) * 32;
        const float* g = Q + (long)(b * SEQ + q0 + row) * EMB + h * HD + c0;
        uint32_t s = sa(Qs + row * QSTR + c0);
#pragma unroll
        for (int j = 0; j < 8; j++) cpa16(s + j * 16, g + j * 4);
    }
    // K (s-major, d interleaved) / V (d-major, s interleaved) tile 0
    {
        int row = tid >> 2;
        int c0 = (tid & 3) * 16;
        const float* kg = K + (long)(b * SEQ + row) * EMB + h * HD + c0;
        uint32_t ksm = sa(Ks + row * KSTR + c0);
#pragma unroll
        for (int j = 0; j < 4; j++) cpa16(ksm + j * 16, kg + j * 4);
        const float* vg = Vt + ((long)bh * HD + row) * SEQ + c0;
        uint32_t vsm = sa(Vs + row * VSTR + c0);
#pragma unroll
        for (int j = 0; j < 4; j++) cpa16(vsm + j * 16, vg + j * 4);
    }
    cp_commit();
    cp_wait0();
    __syncthreads();

    // hoist Q fragments
    unsigned aq[8][4];
#pragma unroll
    for (int ks = 0; ks < 8; ks++) {
        int r0 = w * 16;
        int k0 = ks * 8;
        aq[ks][0] = __float_as_uint(Qs[(r0 + gid)     * QSTR + k0 + tig]);
        aq[ks][1] = __float_as_uint(Qs[(r0 + gid + 8) * QSTR + k0 + tig]);
        aq[ks][2] = __float_as_uint(Qs[(r0 + gid)     * QSTR + k0 + tig + 4]);
        aq[ks][3] = __float_as_uint(Qs[(r0 + gid + 8) * QSTR + k0 + tig + 4]);
    }

    float o[8][4];
#pragma unroll
    for (int dt = 0; dt < 8; dt++)
#pragma unroll
        for (int r = 0; r < 4; r++) o[dt][r] = 0.0f;
    float mA = -1e30f, mB = -1e30f, lA = 0.0f, lB = 0.0f;

    const int src_lo = (lane & ~3) | (tig >> 1);
    const int src_hi = src_lo + 2;
    const bool odd = (tig & 1);

    for (int kt = 0; kt < NKT; kt++) {
        if (kt + 1 < NKT) {
            int nb = (kt + 1) & 1;
            int row = tid >> 2;
            int c0 = (tid & 3) * 16;
            const float* kg = K + (long)(b * SEQ + (kt + 1) * BKV + row) * EMB + h * HD + c0;
            uint32_t ksm = sa(Ks + nb * BKV * KSTR + row * KSTR + c0);
#pragma unroll
            for (int j = 0; j < 4; j++) cpa16(ksm + j * 16, kg + j * 4);
            const float* vg = Vt + ((long)bh * HD + row) * SEQ + (kt + 1) * BKV + c0;
            uint32_t vsm = sa(Vs + nb * HD * VSTR + row * VSTR + c0);
#pragma unroll
            for (int j = 0; j < 4; j++) cpa16(vsm + j * 16, vg + j * 4);
            cp_commit();
        }

        const float* Kb = Ks + (kt & 1) * BKV * KSTR;
        const float* Vb = Vs + (kt & 1) * HD * VSTR;

        // S = Q K^T  (K d-dim interleaved: pair (tig, tig+4) -> float2 at 2*tig)
        float s[8][4];
#pragma unroll
        for (int nt = 0; nt < 8; nt++) {
            s[nt][0] = s[nt][1] = s[nt][2] = s[nt][3] = 0.0f;
#pragma unroll
            for (int ks = 0; ks < 8; ks++) {
                float2 kb2 = *(const float2*)&Kb[(nt * 8 + gid) * KSTR + ks * 8 + 2 * tig];
                unsigned bk[2];
                bk[0] = __float_as_uint(kb2.x);
                bk[1] = __float_as_uint(kb2.y);
                mma_tf32(s[nt], aq[ks], bk);
            }
        }

        // mask (only when tile contains zeros)
        if (!msum[qt * NKT + kt]) {
            int qrA = q0 + w * 16 + gid;
            int qrB = qrA + 8;
#pragma unroll
            for (int nt = 0; nt < 8; nt++) {
                int kc = kt * 64 + nt * 8 + tig * 2;
                const int* mpA = mask + (long)qrA * SEQ + kc;
                const int* mpB = mask + (long)qrB * SEQ + kc;
                if (mpA[0] == 0) s[nt][0] = -1e30f;
                if (mpA[1] == 0) s[nt][1] = -1e30f;
                if (mpB[0] == 0) s[nt][2] = -1e30f;
                if (mpB[1] == 0) s[nt][3] = -1e30f;
            }
        }

        // online softmax (rows gid / gid+8)
        float mxA = -1e30f, mxB = -1e30f;
#pragma unroll
        for (int nt = 0; nt < 8; nt++) {
            mxA = fmaxf(mxA, fmaxf(s[nt][0], s[nt][1]));
            mxB = fmaxf(mxB, fmaxf(s[nt][2], s[nt][3]));
        }
#pragma unroll
        for (int off = 1; off < 4; off <<= 1) {
            mxA = fmaxf(mxA, __shfl_xor_sync(0xffffffffu, mxA, off));
            mxB = fmaxf(mxB, __shfl_xor_sync(0xffffffffu, mxB, off));
        }
        float mnA = fmaxf(mA, mxA), mnB = fmaxf(mB, mxB);
        float fA = __expf(mA - mnA), fB = __expf(mB - mnB);
        mA = mnA; mB = mnB;
        float sumA = 0.0f, sumB = 0.0f;
#pragma unroll
        for (int nt = 0; nt < 8; nt++) {
            s[nt][0] = __expf(s[nt][0] - mA);
            s[nt][1] = __expf(s[nt][1] - mA);
            s[nt][2] = __expf(s[nt][2] - mB);
            s[nt][3] = __expf(s[nt][3] - mB);
            sumA += s[nt][0] + s[nt][1];
            sumB += s[nt][2] + s[nt][3];
        }
#pragma unroll
        for (int off = 1; off < 4; off <<= 1) {
            sumA += __shfl_xor_sync(0xffffffffu, sumA, off);
            sumB += __shfl_xor_sync(0xffffffffu, sumB, off);
        }
        lA = lA * fA + sumA;
        lB = lB * fB + sumB;
#pragma unroll
        for (int dt = 0; dt < 8; dt++) {
            o[dt][0] *= fA; o[dt][1] *= fA;
            o[dt][2] *= fB; o[dt][3] *= fB;
        }

        // tf32-round P in registers
        unsigned up[8][4];
#pragma unroll
        for (int nt = 0; nt < 8; nt++) {
            up[nt][0] = f2tf32(s[nt][0]);
            up[nt][1] = f2tf32(s[nt][1]);
            up[nt][2] = f2tf32(s[nt][2]);
            up[nt][3] = f2tf32(s[nt][3]);
        }

        // O += P V  (A via quad shuffles; V d-major with s interleaved -> LDS.64)
#pragma unroll
        for (int ks = 0; ks < 8; ks++) {
            unsigned e0 = __shfl_sync(0xffffffffu, up[ks][0], src_lo);
            unsigned o0 = __shfl_sync(0xffffffffu, up[ks][1], src_lo);
            unsigned e1 = __shfl_sync(0xffffffffu, up[ks][2], src_lo);
            unsigned o1 = __shfl_sync(0xffffffffu, up[ks][3], src_lo);
            unsigned e2 = __shfl_sync(0xffffffffu, up[ks][0], src_hi);
            unsigned o2 = __shfl_sync(0xffffffffu, up[ks][1], src_hi);
            unsigned e3 = __shfl_sync(0xffffffffu, up[ks][2], src_hi);
            unsigned o3 = __shfl_sync(0xffffffffu, up[ks][3], src_hi);
            unsigned ap[4];
            ap[0] = odd ? o0 : e0;
            ap[1] = odd ? o1 : e1;
            ap[2] = odd ? o2 : e2;
            ap[3] = odd ? o3 : e3;
            int k0 = ks * 8;
#pragma unroll
            for (int dt = 0; dt < 8; dt++) {
                float2 vb2 = *(const float2*)&Vb[(dt * 8 + gid) * VSTR + k0 + 2 * tig];
                unsigned bv[2];
                bv[0] = __float_as_uint(vb2.x);
                bv[1] = __float_as_uint(vb2.y);
                mma_tf32(o[dt], ap, bv);
            }
        }

        if (kt + 1 < NKT) {
            cp_wait0();
            __syncthreads();
        }
    }

    // finalize (tf32-round ctx so the output GEMM can consume raw bits)
    float invA = 1.0f / lA, invB = 1.0f / lB;
    long rowA = (long)(b * SEQ + q0 + w * 16 + gid) * EMB;
    long rowB = rowA + 8L * EMB;
#pragma unroll
    for (int dt = 0; dt < 8; dt++) {
        int gn = h * HD + dt * 8 + tig * 2;
        *(float2*)(ctx + rowA + gn) =
            make_float2(tf32f(o[dt][0] * invA), tf32f(o[dt][1] * invA));
        *(float2*)(ctx + rowB + gn) =
            make_float2(tf32f(o[dt][2] * invB), tf32f(o[dt][3] * invB));
    }
}

// ---------------- launch ----------------------------------------------------
extern "C" void kernel_launch(void* const* d_in, const int* in_sizes, int n_in,
                              void* d_out, int out_size)
{
    const float* x    = (const float*)d_in[0];
    const int*   mask = (const int*)  d_in[1];
    const float* Wq   = (const float*)d_in[2];
    const float* bq   = (const float*)d_in[3];
    const float* Wk   = (const float*)d_in[4];
    const float* bk   = (const float*)d_in[5];
    const float* Wv   = (const float*)d_in[6];
    const float* bv   = (const float*)d_in[7];
    const float* Wo   = (const float*)d_in[8];
    const float* bo   = (const float*)d_in[9];
    float* out = (float*)d_out;

    float *pWq, *pWk, *pWv, *pWo, *pXr, *pQ, *pK, *pV, *pCtx;
    int* pMsum;
    cudaGetSymbolAddress((void**)&pWq, g_Wq);
    cudaGetSymbolAddress((void**)&pWk, g_Wk);
    cudaGetSymbolAddress((void**)&pWv, g_Wv);
    cudaGetSymbolAddress((void**)&pWo, g_Wo);
    cudaGetSymbolAddress((void**)&pXr, g_xr);
    cudaGetSymbolAddress((void**)&pQ,  g_Q);
    cudaGetSymbolAddress((void**)&pK,  g_K);
    cudaGetSymbolAddress((void**)&pV,  g_V);
    cudaGetSymbolAddress((void**)&pCtx, g_ctx);
    cudaGetSymbolAddress((void**)&pMsum, g_msum);

    const int gemm_smem  = (2*128*ASTR + 2*32*BSTR) * (int)sizeof(float);
    const int flash_smem = (BQ*QSTR + 2*BKV*KSTR + 2*HD*VSTR) * (int)sizeof(float);
    cudaFuncSetAttribute(gemm_tf32, cudaFuncAttributeMaxDynamicSharedMemorySize, gemm_smem);
    cudaFuncSetAttribute(flash_tf32, cudaFuncAttributeMaxDynamicSharedMemorySize, flash_smem);

    // 1. prolog: expand weights, pre-round x, mask summary
    Exp4 e;
    e.W[0] = Wq; e.W[1] = Wk; e.W[2] = Wv; e.W[3] = Wo;
    e.Wb[0] = pWq; e.Wb[1] = pWk; e.Wb[2] = pWv; e.Wb[3] = pWo;
    expand4_kernel<<<dim3(NBQ*NBQ/256, 4), 256>>>(e);
    round_kernel<<<(NROWS*EMB/4 + 255)/256, 256>>>(x, pXr, NROWS*EMB/4);
    mask_summary<<<NQT*NKT, 256>>>(mask, pMsum);

    // 2. fused Q/K/V projections
    GemmArgs qkv;
    qkv.A = pXr;
    qkv.W[0] = pWq; qkv.W[1] = pWk; qkv.W[2] = pWv;
    qkv.bias[0] = bq; qkv.bias[1] = bk; qkv.bias[2] = bv;
    qkv.out[0] = pQ; qkv.out[1] = pK; qkv.out[2] = pV;
    qkv.oscale[0] = 0.125f; qkv.oscale[1] = 1.0f; qkv.oscale[2] = 1.0f;
    qkv.mode[0] = 0; qkv.mode[1] = 1; qkv.mode[2] = 2;
    qkv.round_out = 1;
    dim3 ggrid(EMB/128, NROWS/128, 3);
    gemm_tf32<<<ggrid, 256, gemm_smem>>>(qkv);

    // 3. attention
    dim3 agrid(SEQ/BQ, NH, NBATCH);
    flash_tf32<<<agrid, 256, flash_smem>>>(pQ, pK, pV, mask, pMsum, pCtx);

    // 4. output projection -> d_out
    GemmArgs og;
    og.A = pCtx;
    og.W[0] = pWo; og.W[1] = pWo; og.W[2] = pWo;
    og.bias[0] = bo; og.bias[1] = bo; og.bias[2] = bo;
    og.out[0] = out; og.out[1] = out; og.out[2] = out;
    og.oscale[0] = 1.0f; og.oscale[1] = 1.0f; og.oscale[2] = 1.0f;
    og.mode[0] = 0; og.mode[1] = 0; og.mode[2] = 0;
    og.round_out = 0;
    dim3 ogrid(EMB/128, NROWS/128, 1);
    gemm_tf32<<<ogrid, 256, gemm_smem>>>(og);
}

// round 7
// speedup vs baseline: 1.1335x; 1.1335x over previous
#include <cuda_runtime.h>
#include <cstdint>
#include <math.h>

#define SEQ 2048
#define EMB 1024
#define NBQ 256
#define NH 16
#define HD 64
#define NBATCH 2
#define NROWS (NBATCH*SEQ)   // 4096
#define NKT (SEQ/64)         // 32 kv tiles
#define NQT (SEQ/128)        // 16 q tiles

// ---------------- scratch (device globals) ---------------------------------
__device__ float g_Wq[EMB*EMB];      // transposed [out][in], k-interleaved
__device__ float g_Wk[EMB*EMB];
__device__ float g_Wv[EMB*EMB];
__device__ float g_Wo[EMB*EMB];
__device__ float g_xr[NROWS*EMB];    // tf32-rounded, k-interleaved
__device__ float g_Q[NROWS*EMB];     // plain
__device__ float g_K[NROWS*EMB];     // head-dim interleaved within 8-groups
__device__ float g_V[NROWS*EMB];     // plain (s-major)
__device__ float g_Vt[NROWS*EMB];    // [b,h,d,s], s interleaved within 8-groups
__device__ float g_ctx[NROWS*EMB];   // tf32-rounded, k-interleaved
__device__ int   g_msum[NQT*NKT];

// ---------------- helpers ---------------------------------------------------
__device__ __forceinline__ unsigned f2tf32(float x) {
    unsigned u;
    asm("cvt.rna.tf32.f32 %0, %1;" : "=r"(u) : "f"(x));
    return u;
}
__device__ __forceinline__ float tf32f(float x) { return __uint_as_float(f2tf32(x)); }

// interleave within an 8-group: 0..3 -> 0,2,4,6 ; 4..7 -> 1,3,5,7
__device__ __forceinline__ int perm8(int c) {
    int c8 = c & 7;
    return (c & ~7) | ((c8 < 4) ? (2 * c8) : (2 * (c8 - 4) + 1));
}

__device__ __forceinline__ void mma_tf32(float* d, const unsigned* a, const unsigned* b) {
    asm volatile(
        "mma.sync.aligned.m16n8k8.row.col.f32.tf32.tf32.f32 "
        "{%0,%1,%2,%3},{%4,%5,%6,%7},{%8,%9},{%0,%1,%2,%3};"
        : "+f"(d[0]), "+f"(d[1]), "+f"(d[2]), "+f"(d[3])
        : "r"(a[0]), "r"(a[1]), "r"(a[2]), "r"(a[3]), "r"(b[0]), "r"(b[1]));
}

__device__ __forceinline__ uint32_t sa(const void* p) {
    return (uint32_t)__cvta_generic_to_shared(p);
}
__device__ __forceinline__ void cpa16(uint32_t s, const void* g) {
    asm volatile("cp.async.cg.shared.global [%0], [%1], 16;" :: "r"(s), "l"(g));
}
__device__ __forceinline__ void cp_commit() {
    asm volatile("cp.async.commit_group;" ::: "memory");
}
__device__ __forceinline__ void cp_wait0() {
    asm volatile("cp.async.wait_group 0;" ::: "memory");
}

// ---------------- x pre-round to tf32 + k-interleave ------------------------
__global__ void round_kernel(const float* __restrict__ in, float* __restrict__ outp, int n4) {
    int i = blockIdx.x * blockDim.x + threadIdx.x;
    if (i >= n4) return;
    float4 v = ((const float4*)in)[i];
    int c = i * 4;                 // 4-aligned: all 4 in same 8-group half
    int row = c / EMB, col = c % EMB;
    float* o = outp + (long)row * EMB;
    o[perm8(col + 0)] = tf32f(v.x);
    o[perm8(col + 1)] = tf32f(v.y);
    o[perm8(col + 2)] = tf32f(v.z);
    o[perm8(col + 3)] = tf32f(v.w);
}

// ---------------- weight expansion: transposed [out][in], k-interleaved -----
struct Exp4 { const float* W[4]; float* Wb[4]; };

__global__ void expand4_kernel(Exp4 e) {
    int z = blockIdx.y;
    int idx = blockIdx.x * blockDim.x + threadIdx.x;
    if (idx >= NBQ * NBQ) return;
    int o = idx / NBQ;
    int n = idx % NBQ;
    const float* w = e.W[z] + (o * NBQ + n) * 4;
    float w0 = tf32f(w[0]), w1 = tf32f(w[1]), w2 = tf32f(w[2]), w3 = tf32f(w[3]);
    // M[j][k]: in-row j, out-col k (quaternion left-mult)
    float M[4][4] = {{ w0,  w1,  w2,  w3},
                     {-w1,  w0,  w3, -w2},
                     {-w2, -w3,  w0,  w1},
                     {-w3,  w2, -w1,  w0}};
    // WT[out = o*4+k][in-col = (n&~1)*4 + 2j + (n&1)]
    float* Wb = e.Wb[z];
    int cbase = (n & ~1) * 4 + (n & 1);
#pragma unroll
    for (int k = 0; k < 4; k++) {
        float* row = Wb + (long)(o * 4 + k) * EMB + cbase;
#pragma unroll
        for (int j = 0; j < 4; j++) row[2 * j] = M[j][k];
    }
}

// ---------------- mask tile summary (128q x 64k tiles) ----------------------
__global__ void mask_summary(const int* __restrict__ mask, int* __restrict__ sum) {
    int tile = blockIdx.x;
    int qt = tile / NKT, kt = tile % NKT;
    int tid = threadIdx.x;
    int ok = 1;
    for (int i = tid; i < 128*64; i += 256) {
        int r = i / 64, c = i % 64;
        ok &= (mask[(qt*128 + r) * SEQ + kt*64 + c] != 0);
    }
    int allok = __syncthreads_and(ok);
    if (tid == 0) sum[tile] = allok;
}

// ---------------- V transpose: [b,s,h,d] -> [b,h,d,s(perm8)] -----------------
__global__ __launch_bounds__(256) void vtrans_kernel(
    const float* __restrict__ V, float* __restrict__ Vt)
{
    __shared__ float Ts[64][68];
    int bh = blockIdx.y;               // b*NH + h
    int b = bh / NH, h = bh % NH;
    int st = blockIdx.x * 64;
    int tid = threadIdx.x;
    int i = tid >> 2;                  // s-local 0..63
    int j0 = (tid & 3) * 16;           // d-chunk
    const float* src = V + (long)(b * SEQ + st + i) * EMB + h * HD + j0;
    int ip = perm8(i);
#pragma unroll
    for (int c = 0; c < 4; c++) {
        float4 v = *(const float4*)(src + c * 4);
        Ts[j0 + c*4 + 0][ip] = v.x;
        Ts[j0 + c*4 + 1][ip] = v.y;
        Ts[j0 + c*4 + 2][ip] = v.z;
        Ts[j0 + c*4 + 3][ip] = v.w;
    }
    __syncthreads();
    int d = tid >> 2;                  // 0..63
    int s0 = (tid & 3) * 16;
    float* dst = Vt + ((long)bh * HD + d) * SEQ + st + s0;
#pragma unroll
    for (int c = 0; c < 4; c++)
        *(float4*)(dst + c * 4) = *(const float4*)&Ts[d][s0 + c * 4];
}

// ---------------- TF32 GEMM (cp.async, vectorized LDS.64 frags) -------------
// A: [M][K] k-interleaved tf32.  W: transposed [N][K] k-interleaved tf32.
#define ASTR 40
#define BSTR 40

struct GemmArgs {
    const float* A;
    const float* W[3];
    const float* bias[3];
    float* out[3];
    float oscale[3];
    int   mode[3];     // 0 = plain, 1 = K head-dim perm8, 2 = ctx perm8
    int   round_out;
};

__global__ __launch_bounds__(256, 2) void gemm_tf32(GemmArgs ga) {
    extern __shared__ float gs[];
    float* Asm = gs;                       // 2 * 128*ASTR
    float* Bsm = gs + 2 * 128 * ASTR;      // 2 * 128*BSTR

    int tid = threadIdx.x;
    int z = blockIdx.z;
    const float* A = ga.A;
    const float* W = ga.W[z];
    const float* bias = ga.bias[z];
    float* C = ga.out[z];

    int bm = blockIdx.y * 128;
    int bn = blockIdx.x * 128;
    int warp = tid / 32, lane = tid % 32;
    int gid = lane >> 2, tig = lane & 3;
    int wm = (warp / 4) * 64, wn = (warp % 4) * 32;

    int r128 = tid >> 1;           // 0..127
    int ch   = (tid & 1) * 16;     // 16-float half

    float acc[4][4][4];
#pragma unroll
    for (int mt = 0; mt < 4; mt++)
#pragma unroll
        for (int nt = 0; nt < 4; nt++)
#pragma unroll
            for (int r = 0; r < 4; r++) acc[mt][nt][r] = 0.0f;

#define GLOAD(kt, buf)                                                         \
    {                                                                          \
        const float* asrc = A + (long)(bm + r128) * EMB + (kt) * 32 + ch;      \
        uint32_t adst = sa(Asm + (buf) * 128 * ASTR + r128 * ASTR + ch);       \
        _Pragma("unroll")                                                      \
        for (int j = 0; j < 4; j++) cpa16(adst + j * 16, asrc + j * 4);        \
        const float* bsrc = W + (long)(bn + r128) * EMB + (kt) * 32 + ch;      \
        uint32_t bdst = sa(Bsm + (buf) * 128 * BSTR + r128 * BSTR + ch);       \
        _Pragma("unroll")                                                      \
        for (int j = 0; j < 4; j++) cpa16(bdst + j * 16, bsrc + j * 4);        \
    }

    GLOAD(0, 0);
    cp_commit();
    cp_wait0();
    __syncthreads();

    for (int kt = 0; kt < EMB / 32; kt++) {
        if (kt + 1 < EMB / 32) {
            GLOAD(kt + 1, (kt + 1) & 1);
            cp_commit();
        }

        const float* As = Asm + (kt & 1) * 128 * ASTR;
        const float* Bs = Bsm + (kt & 1) * 128 * BSTR;
#pragma unroll
        for (int ks = 0; ks < 4; ks++) {
            int k0 = ks * 8 + 2 * tig;
            unsigned af[4][4], bf[4][2];
#pragma unroll
            for (int mt = 0; mt < 4; mt++) {
                int r0 = wm + mt * 16;
                float2 aLo = *(const float2*)&As[(r0 + gid)     * ASTR + k0];
                float2 aHi = *(const float2*)&As[(r0 + gid + 8) * ASTR + k0];
                af[mt][0] = __float_as_uint(aLo.x);
                af[mt][1] = __float_as_uint(aHi.x);
                af[mt][2] = __float_as_uint(aLo.y);
                af[mt][3] = __float_as_uint(aHi.y);
            }
#pragma unroll
            for (int nt = 0; nt < 4; nt++) {
                int c0 = wn + nt * 8;
                float2 b2 = *(const float2*)&Bs[(c0 + gid) * BSTR + k0];
                bf[nt][0] = __float_as_uint(b2.x);
                bf[nt][1] = __float_as_uint(b2.y);
            }
#pragma unroll
            for (int mt = 0; mt < 4; mt++)
#pragma unroll
                for (int nt = 0; nt < 4; nt++)
                    mma_tf32(acc[mt][nt], af[mt], bf[nt]);
        }
        if (kt + 1 < EMB / 32) {
            cp_wait0();
            __syncthreads();
        }
    }

    float os = ga.oscale[z];
    int rnd = ga.round_out;
    int mode = ga.mode[z];
#pragma unroll
    for (int mt = 0; mt < 4; mt++)
#pragma unroll
        for (int nt = 0; nt < 4; nt++) {
            int gm = bm + wm + mt * 16 + gid;
            int gn = bn + wn + nt * 8 + tig * 2;
            float b0 = bias[gn], b1 = bias[gn + 1];
            float v0 = (acc[mt][nt][0] + b0) * os;
            float v1 = (acc[mt][nt][1] + b1) * os;
            float v2 = (acc[mt][nt][2] + b0) * os;
            float v3 = (acc[mt][nt][3] + b1) * os;
            if (rnd) { v0 = tf32f(v0); v1 = tf32f(v1); v2 = tf32f(v2); v3 = tf32f(v3); }
            if (mode == 0) {
                *(float2*)(C + (long)gm * EMB + gn) = make_float2(v0, v1);
                *(float2*)(C + (long)(gm + 8) * EMB + gn) = make_float2(v2, v3);
            } else {
                // perm8 within-row scatter (same 32B sector; modes 1 and 2)
                int p0 = perm8(gn), p1 = perm8(gn + 1);
                C[(long)gm * EMB + p0] = v0;
                C[(long)gm * EMB + p1] = v1;
                C[(long)(gm + 8) * EMB + p0] = v2;
                C[(long)(gm + 8) * EMB + p1] = v3;
            }
        }
}

// ---------------- TF32 flash attention (LDS.64 frags, conflict-free) --------
#define BQ 128
#define BKV 64
#define QSTR 68
#define KSTR 72
#define VSTR 72

__global__ __launch_bounds__(256, 2) void flash_tf32(
    const float* __restrict__ Q, const float* __restrict__ K,
    const float* __restrict__ Vt, const int* __restrict__ mask,
    const int* __restrict__ msum, float* __restrict__ ctx)
{
    extern __shared__ float fs[];
    float* Qs = fs;                         // BQ*QSTR
    float* Ks = Qs + BQ * QSTR;             // 2*BKV*KSTR
    float* Vs = Ks + 2 * BKV * KSTR;        // 2*HD*VSTR (d-major)

    int tid = threadIdx.x;
    int w = tid / 32, lane = tid % 32;
    int gid = lane >> 2, tig = lane & 3;
    int qt = blockIdx.x, h = blockIdx.y, b = blockIdx.z;
    int q0 = qt * BQ;
    int bh = b * NH + h;

    // Q tile (tf32-rounded + pre-scaled, plain layout)
    {
        int row = tid >> 1;
        int c0 = (tid & 1) * 32;
        const float* g = Q + (long)(b * SEQ + q0 + row) * EMB + h * HD + c0;
        uint32_t s = sa(Qs + row * QSTR + c0);
#pragma unroll
        for (int j = 0; j < 8; j++) cpa16(s + j * 16, g + j * 4);
    }
    // K (s-major, d interleaved) / Vt (d-major, s interleaved) tile 0
    {
        int row = tid >> 2;
        int c0 = (tid & 3) * 16;
        const float* kg = K + (long)(b * SEQ + row) * EMB + h * HD + c0;
        uint32_t ksm = sa(Ks + row * KSTR + c0);
#pragma unroll
        for (int j = 0; j < 4; j++) cpa16(ksm + j * 16, kg + j * 4);
        const float* vg = Vt + ((long)bh * HD + row) * SEQ + c0;
        uint32_t vsm = sa(Vs + row * VSTR + c0);
#pragma unroll
        for (int j = 0; j < 4; j++) cpa16(vsm + j * 16, vg + j * 4);
    }
    cp_commit();
    cp_wait0();
    __syncthreads();

    // hoist Q fragments
    unsigned aq[8][4];
#pragma unroll
    for (int ks = 0; ks < 8; ks++) {
        int r0 = w * 16;
        int k0 = ks * 8;
        aq[ks][0] = __float_as_uint(Qs[(r0 + gid)     * QSTR + k0 + tig]);
        aq[ks][1] = __float_as_uint(Qs[(r0 + gid + 8) * QSTR + k0 + tig]);
        aq[ks][2] = __float_as_uint(Qs[(r0 + gid)     * QSTR + k0 + tig + 4]);
        aq[ks][3] = __float_as_uint(Qs[(r0 + gid + 8) * QSTR + k0 + tig + 4]);
    }

    float o[8][4];
#pragma unroll
    for (int dt = 0; dt < 8; dt++)
#pragma unroll
        for (int r = 0; r < 4; r++) o[dt][r] = 0.0f;
    float mA = -1e30f, mB = -1e30f, lA = 0.0f, lB = 0.0f;

    const int src_lo = (lane & ~3) | (tig >> 1);
    const int src_hi = src_lo + 2;
    const bool odd = (tig & 1);

    for (int kt = 0; kt < NKT; kt++) {
        if (kt + 1 < NKT) {
            int nb = (kt + 1) & 1;
            int row = tid >> 2;
            int c0 = (tid & 3) * 16;
            const float* kg = K + (long)(b * SEQ + (kt + 1) * BKV + row) * EMB + h * HD + c0;
            uint32_t ksm = sa(Ks + nb * BKV * KSTR + row * KSTR + c0);
#pragma unroll
            for (int j = 0; j < 4; j++) cpa16(ksm + j * 16, kg + j * 4);
            const float* vg = Vt + ((long)bh * HD + row) * SEQ + (kt + 1) * BKV + c0;
            uint32_t vsm = sa(Vs + nb * HD * VSTR + row * VSTR + c0);
#pragma unroll
            for (int j = 0; j < 4; j++) cpa16(vsm + j * 16, vg + j * 4);
            cp_commit();
        }

        const float* Kb = Ks + (kt & 1) * BKV * KSTR;
        const float* Vb = Vs + (kt & 1) * HD * VSTR;

        // S = Q K^T  (K interleaved: (tig, tig+4) adjacent -> LDS.64)
        float s[8][4];
#pragma unroll
        for (int nt = 0; nt < 8; nt++) {
            s[nt][0] = s[nt][1] = s[nt][2] = s[nt][3] = 0.0f;
#pragma unroll
            for (int ks = 0; ks < 8; ks++) {
                float2 kb2 = *(const float2*)&Kb[(nt * 8 + gid) * KSTR + ks * 8 + 2 * tig];
                unsigned bk[2];
                bk[0] = __float_as_uint(kb2.x);
                bk[1] = __float_as_uint(kb2.y);
                mma_tf32(s[nt], aq[ks], bk);
            }
        }

        // mask (only when tile contains zeros)
        if (!msum[qt * NKT + kt]) {
            int qrA = q0 + w * 16 + gid;
            int qrB = qrA + 8;
#pragma unroll
            for (int nt = 0; nt < 8; nt++) {
                int kc = kt * 64 + nt * 8 + tig * 2;
                const int* mpA = mask + (long)qrA * SEQ + kc;
                const int* mpB = mask + (long)qrB * SEQ + kc;
                if (mpA[0] == 0) s[nt][0] = -1e30f;
                if (mpA[1] == 0) s[nt][1] = -1e30f;
                if (mpB[0] == 0) s[nt][2] = -1e30f;
                if (mpB[1] == 0) s[nt][3] = -1e30f;
            }
        }

        // online softmax (rows gid / gid+8)
        float mxA = -1e30f, mxB = -1e30f;
#pragma unroll
        for (int nt = 0; nt < 8; nt++) {
            mxA = fmaxf(mxA, fmaxf(s[nt][0], s[nt][1]));
            mxB = fmaxf(mxB, fmaxf(s[nt][2], s[nt][3]));
        }
#pragma unroll
        for (int off = 1; off < 4; off <<= 1) {
            mxA = fmaxf(mxA, __shfl_xor_sync(0xffffffffu, mxA, off));
            mxB = fmaxf(mxB, __shfl_xor_sync(0xffffffffu, mxB, off));
        }
        float mnA = fmaxf(mA, mxA), mnB = fmaxf(mB, mxB);
        float fA = __expf(mA - mnA), fB = __expf(mB - mnB);
        mA = mnA; mB = mnB;
        float sumA = 0.0f, sumB = 0.0f;
#pragma unroll
        for (int nt = 0; nt < 8; nt++) {
            s[nt][0] = __expf(s[nt][0] - mA);
            s[nt][1] = __expf(s[nt][1] - mA);
            s[nt][2] = __expf(s[nt][2] - mB);
            s[nt][3] = __expf(s[nt][3] - mB);
            sumA += s[nt][0] + s[nt][1];
            sumB += s[nt][2] + s[nt][3];
        }
#pragma unroll
        for (int off = 1; off < 4; off <<= 1) {
            sumA += __shfl_xor_sync(0xffffffffu, sumA, off);
            sumB += __shfl_xor_sync(0xffffffffu, sumB, off);
        }
        lA = lA * fA + sumA;
        lB = lB * fB + sumB;
#pragma unroll
        for (int dt = 0; dt < 8; dt++) {
            o[dt][0] *= fA; o[dt][1] *= fA;
            o[dt][2] *= fB; o[dt][3] *= fB;
        }

        // tf32-round P in registers
        unsigned up[8][4];
#pragma unroll
        for (int nt = 0; nt < 8; nt++) {
            up[nt][0] = f2tf32(s[nt][0]);
            up[nt][1] = f2tf32(s[nt][1]);
            up[nt][2] = f2tf32(s[nt][2]);
            up[nt][3] = f2tf32(s[nt][3]);
        }

        // O += P V  (A via quad shuffles; V d-major s-interleaved -> LDS.64)
#pragma unroll
        for (int ks = 0; ks < 8; ks++) {
            unsigned e0 = __shfl_sync(0xffffffffu, up[ks][0], src_lo);
            unsigned o0 = __shfl_sync(0xffffffffu, up[ks][1], src_lo);
            unsigned e1 = __shfl_sync(0xffffffffu, up[ks][2], src_lo);
            unsigned o1 = __shfl_sync(0xffffffffu, up[ks][3], src_lo);
            unsigned e2 = __shfl_sync(0xffffffffu, up[ks][0], src_hi);
            unsigned o2 = __shfl_sync(0xffffffffu, up[ks][1], src_hi);
            unsigned e3 = __shfl_sync(0xffffffffu, up[ks][2], src_hi);
            unsigned o3 = __shfl_sync(0xffffffffu, up[ks][3], src_hi);
            unsigned ap[4];
            ap[0] = odd ? o0 : e0;
            ap[1] = odd ? o1 : e1;
            ap[2] = odd ? o2 : e2;
            ap[3] = odd ? o3 : e3;
            int k0 = ks * 8;
#pragma unroll
            for (int dt = 0; dt < 8; dt++) {
                float2 vb2 = *(const float2*)&Vb[(dt * 8 + gid) * VSTR + k0 + 2 * tig];
                unsigned bv[2];
                bv[0] = __float_as_uint(vb2.x);
                bv[1] = __float_as_uint(vb2.y);
                mma_tf32(o[dt], ap, bv);
            }
        }

        if (kt + 1 < NKT) {
            cp_wait0();
            __syncthreads();
        }
    }

    // finalize: tf32-round + perm8 columns (ctx is outproj's A operand)
    float invA = 1.0f / lA, invB = 1.0f / lB;
    long rowA = (long)(b * SEQ + q0 + w * 16 + gid) * EMB;
    long rowB = rowA + 8L * EMB;
#pragma unroll
    for (int dt = 0; dt < 8; dt++) {
        int gn = h * HD + dt * 8 + tig * 2;
        int p0 = perm8(gn), p1 = perm8(gn + 1);
        ctx[rowA + p0] = tf32f(o[dt][0] * invA);
        ctx[rowA + p1] = tf32f(o[dt][1] * invA);
        ctx[rowB + p0] = tf32f(o[dt][2] * invB);
        ctx[rowB + p1] = tf32f(o[dt][3] * invB);
    }
}

// ---------------- launch ----------------------------------------------------
extern "C" void kernel_launch(void* const* d_in, const int* in_sizes, int n_in,
                              void* d_out, int out_size)
{
    const float* x    = (const float*)d_in[0];
    const int*   mask = (const int*)  d_in[1];
    const float* Wq   = (const float*)d_in[2];
    const float* bq   = (const float*)d_in[3];
    const float* Wk   = (const float*)d_in[4];
    const float* bk   = (const float*)d_in[5];
    const float* Wv   = (const float*)d_in[6];
    const float* bv   = (const float*)d_in[7];
    const float* Wo   = (const float*)d_in[8];
    const float* bo   = (const float*)d_in[9];
    float* out = (float*)d_out;

    float *pWq, *pWk, *pWv, *pWo, *pXr, *pQ, *pK, *pV, *pVt, *pCtx;
    int* pMsum;
    cudaGetSymbolAddress((void**)&pWq, g_Wq);
    cudaGetSymbolAddress((void**)&pWk, g_Wk);
    cudaGetSymbolAddress((void**)&pWv, g_Wv);
    cudaGetSymbolAddress((void**)&pWo, g_Wo);
    cudaGetSymbolAddress((void**)&pXr, g_xr);
    cudaGetSymbolAddress((void**)&pQ,  g_Q);
    cudaGetSymbolAddress((void**)&pK,  g_K);
    cudaGetSymbolAddress((void**)&pV,  g_V);
    cudaGetSymbolAddress((void**)&pVt, g_Vt);
    cudaGetSymbolAddress((void**)&pCtx, g_ctx);
    cudaGetSymbolAddress((void**)&pMsum, g_msum);

    const int gemm_smem  = (2*128*ASTR + 2*128*BSTR) * (int)sizeof(float);           // 80KB
    const int flash_smem = (BQ*QSTR + 2*BKV*KSTR + 2*HD*VSTR) * (int)sizeof(float);  // ~108KB
    cudaFuncSetAttribute(gemm_tf32, cudaFuncAttributeMaxDynamicSharedMemorySize, gemm_smem);
    cudaFuncSetAttribute(flash_tf32, cudaFuncAttributeMaxDynamicSharedMemorySize, flash_smem);

    // 1. prolog
    Exp4 e;
    e.W[0] = Wq; e.W[1] = Wk; e.W[2] = Wv; e.W[3] = Wo;
    e.Wb[0] = pWq; e.Wb[1] = pWk; e.Wb[2] = pWv; e.Wb[3] = pWo;
    expand4_kernel<<<dim3(NBQ*NBQ/256, 4), 256>>>(e);
    round_kernel<<<(NROWS*EMB/4 + 255)/256, 256>>>(x, pXr, NROWS*EMB/4);
    mask_summary<<<NQT*NKT, 256>>>(mask, pMsum);

    // 2. fused Q/K/V projections (Q: plain+prescaled; K: perm8; V: plain)
    GemmArgs qkv;
    qkv.A = pXr;
    qkv.W[0] = pWq; qkv.W[1] = pWk; qkv.W[2] = pWv;
    qkv.bias[0] = bq; qkv.bias[1] = bk; qkv.bias[2] = bv;
    qkv.out[0] = pQ; qkv.out[1] = pK; qkv.out[2] = pV;
    qkv.oscale[0] = 0.125f; qkv.oscale[1] = 1.0f; qkv.oscale[2] = 1.0f;
    qkv.mode[0] = 0; qkv.mode[1] = 1; qkv.mode[2] = 0;
    qkv.round_out = 1;
    dim3 ggrid(EMB/128, NROWS/128, 3);
    gemm_tf32<<<ggrid, 256, gemm_smem>>>(qkv);

    // 2b. transpose V -> [b,h,d,s(perm8)]
    vtrans_kernel<<<dim3(SEQ/64, NBATCH*NH), 256>>>(pV, pVt);

    // 3. attention
    dim3 agrid(SEQ/BQ, NH, NBATCH);
    flash_tf32<<<agrid, 256, flash_smem>>>(pQ, pK, pVt, mask, pMsum, pCtx);

    // 4. output projection -> d_out
    GemmArgs og;
    og.A = pCtx;
    og.W[0] = pWo; og.W[1] = pWo; og.W[2] = pWo;
    og.bias[0] = bo; og.bias[1] = bo; og.bias[2] = bo;
    og.out[0] = out; og.out[1] = out; og.out[2] = out;
    og.oscale[0] = 1.0f; og.oscale[1] = 1.0f; og.oscale[2] = 1.0f;
    og.mode[0] = 0; og.mode[1] = 0; og.mode[2] = 0;
    og.round_out = 0;
    dim3 ogrid(EMB/128, NROWS/128, 1);
    gemm_tf32<<<ogrid, 256, gemm_smem>>>(og);
}

// round 8
// speedup vs baseline: 2.5139x; 2.2179x over previous
#include <cuda_runtime.h>
#include <cuda_fp16.h>
#include <cstdint>
#include <math.h>

#define SEQ 2048
#define EMB 1024
#define NBQ 256
#define NH 16
#define HD 64
#define NBATCH 2
#define NROWS (NBATCH*SEQ)   // 4096
#define NKT (SEQ/64)         // 32 kv tiles
#define NQT (SEQ/128)        // 16 q tiles

// ---------------- scratch (device globals) ---------------------------------
__device__ __half g_Wq[EMB*EMB];     // transposed [out][in]
__device__ __half g_Wk[EMB*EMB];
__device__ __half g_Wv[EMB*EMB];
__device__ __half g_Wo[EMB*EMB];
__device__ __half g_xr[NROWS*EMB];   // fp16 input
__device__ __half g_Q[NROWS*EMB];    // prescaled by 1/8
__device__ __half g_K[NROWS*EMB];
__device__ __half g_V[NROWS*EMB];    // [b,s,h,d]
__device__ __half g_Vt[NROWS*EMB];   // [b,h,d,s]
__device__ __half g_ctx[NROWS*EMB];
__device__ int    g_msum[NQT*NKT];

// ---------------- helpers ---------------------------------------------------
__device__ __forceinline__ uint32_t h2u(__half2 h) {
    return *reinterpret_cast<uint32_t*>(&h);
}

__device__ __forceinline__ void mma_f16(float* d, const unsigned* a, const unsigned* b) {
    asm volatile(
        "mma.sync.aligned.m16n8k16.row.col.f32.f16.f16.f32 "
        "{%0,%1,%2,%3},{%4,%5,%6,%7},{%8,%9},{%0,%1,%2,%3};"
        : "+f"(d[0]), "+f"(d[1]), "+f"(d[2]), "+f"(d[3])
        : "r"(a[0]), "r"(a[1]), "r"(a[2]), "r"(a[3]), "r"(b[0]), "r"(b[1]));
}

#define LDSM4(r0, r1, r2, r3, addr)                                            \
    asm volatile("ldmatrix.sync.aligned.m8n8.x4.shared.b16 {%0,%1,%2,%3}, [%4];" \
                 : "=r"(r0), "=r"(r1), "=r"(r2), "=r"(r3) : "r"(addr))

__device__ __forceinline__ uint32_t sa(const void* p) {
    return (uint32_t)__cvta_generic_to_shared(p);
}
__device__ __forceinline__ void cpa16(uint32_t s, const void* g) {
    asm volatile("cp.async.cg.shared.global [%0], [%1], 16;" :: "r"(s), "l"(g));
}
__device__ __forceinline__ void cp_commit() {
    asm volatile("cp.async.commit_group;" ::: "memory");
}
__device__ __forceinline__ void cp_wait0() {
    asm volatile("cp.async.wait_group 0;" ::: "memory");
}

// ---------------- x -> fp16 --------------------------------------------------
__global__ void round_kernel(const float* __restrict__ in, __half* __restrict__ outp, int n4) {
    int i = blockIdx.x * blockDim.x + threadIdx.x;
    if (i >= n4) return;
    float4 v = ((const float4*)in)[i];
    __half2* o = (__half2*)(outp + i * 4);
    o[0] = __floats2half2_rn(v.x, v.y);
    o[1] = __floats2half2_rn(v.z, v.w);
}

// ---------------- weight expansion: transposed [out][in], fp16 --------------
struct Exp4 { const float* W[4]; __half* Wb[4]; };

__global__ void expand4_kernel(Exp4 e) {
    int z = blockIdx.y;
    int idx = blockIdx.x * blockDim.x + threadIdx.x;
    if (idx >= NBQ * NBQ) return;
    int o = idx / NBQ;
    int n = idx % NBQ;
    const float* w = e.W[z] + (o * NBQ + n) * 4;
    float w0 = w[0], w1 = w[1], w2 = w[2], w3 = w[3];
    // M[j][k]: in-row j, out-col k. WT[out][in] = M[j][k] at [o*4+k][n*4+j]
    float M[4][4] = {{ w0,  w1,  w2,  w3},
                     {-w1,  w0,  w3, -w2},
                     {-w2, -w3,  w0,  w1},
                     {-w3,  w2, -w1,  w0}};
    __half* Wb = e.Wb[z];
#pragma unroll
    for (int k = 0; k < 4; k++) {
        __half2* row = (__half2*)(Wb + (long)(o * 4 + k) * EMB + n * 4);
        row[0] = __floats2half2_rn(M[0][k], M[1][k]);
        row[1] = __floats2half2_rn(M[2][k], M[3][k]);
    }
}

// ---------------- mask tile summary (128q x 64k tiles) ----------------------
__global__ void mask_summary(const int* __restrict__ mask, int* __restrict__ sum) {
    int tile = blockIdx.x;
    int qt = tile / NKT, kt = tile % NKT;
    int tid = threadIdx.x;
    int ok = 1;
    for (int i = tid; i < 128*64; i += 256) {
        int r = i / 64, c = i % 64;
        ok &= (mask[(qt*128 + r) * SEQ + kt*64 + c] != 0);
    }
    int allok = __syncthreads_and(ok);
    if (tid == 0) sum[tile] = allok;
}

// ---------------- V transpose: [b,s,h,d] -> [b,h,d,s], fp16 -----------------
__global__ __launch_bounds__(256) void vtrans_kernel(
    const __half* __restrict__ V, __half* __restrict__ Vt)
{
    __shared__ __half Ts[64][72];
    int bh = blockIdx.y;
    int b = bh / NH, h = bh % NH;
    int st = blockIdx.x * 64;
    int tid = threadIdx.x;
    int s = tid >> 2;
    int d0 = (tid & 3) * 16;
    const __half* src = V + (long)(b * SEQ + st + s) * EMB + h * HD + d0;
#pragma unroll
    for (int c = 0; c < 16; c++) Ts[d0 + c][s] = src[c];
    __syncthreads();
    int d = tid >> 2;
    int s0 = (tid & 3) * 16;
    __half* dst = Vt + ((long)bh * HD + d) * SEQ + st + s0;
#pragma unroll
    for (int c = 0; c < 2; c++)
        *(uint4*)(dst + c * 8) = *(const uint4*)&Ts[d][s0 + c * 8];
}

// ---------------- FP16 GEMM (cp.async + ldmatrix) ---------------------------
// A: [M][K] half.  W: transposed [N][K] half.  BK=32.
#define ASTR 40   // halves; 80B rows -> ldmatrix conflict-free
#define BSTR 40

struct GemmArgs {
    const __half* A;
    const __half* W[3];
    const float* bias[3];
    void* out[3];
    float oscale[3];
    int   half_out;
};

__global__ __launch_bounds__(256, 2) void gemm_f16(GemmArgs ga) {
    extern __shared__ __half gsm[];
    __half* Asm = gsm;                       // 2 * 128*ASTR
    __half* Bsm = gsm + 2 * 128 * ASTR;      // 2 * 128*BSTR

    int tid = threadIdx.x;
    int z = blockIdx.z;
    const __half* A = ga.A;
    const __half* W = ga.W[z];
    const float* bias = ga.bias[z];

    int bm = blockIdx.y * 128;
    int bn = blockIdx.x * 128;
    int warp = tid / 32, lane = tid % 32;
    int gid = lane >> 2, tig = lane & 3;
    int wm = (warp / 4) * 64, wn = (warp % 4) * 32;
    int lrow = lane & 7, lmat = lane >> 3;

    int r128 = tid >> 1;           // 0..127
    int ch   = (tid & 1) * 16;     // 16-half chunk (32B)

    float acc[4][4][4];
#pragma unroll
    for (int mt = 0; mt < 4; mt++)
#pragma unroll
        for (int nt = 0; nt < 4; nt++)
#pragma unroll
            for (int r = 0; r < 4; r++) acc[mt][nt][r] = 0.0f;

#define GLOAD(kt, buf)                                                         \
    {                                                                          \
        const __half* asrc = A + (long)(bm + r128) * EMB + (kt) * 32 + ch;     \
        uint32_t adst = sa(Asm + (buf) * 128 * ASTR + r128 * ASTR + ch);       \
        cpa16(adst, asrc); cpa16(adst + 16, asrc + 8);                         \
        const __half* bsrc = W + (long)(bn + r128) * EMB + (kt) * 32 + ch;     \
        uint32_t bdst = sa(Bsm + (buf) * 128 * BSTR + r128 * BSTR + ch);       \
        cpa16(bdst, bsrc); cpa16(bdst + 16, bsrc + 8);                         \
    }

    GLOAD(0, 0);
    cp_commit();
    cp_wait0();
    __syncthreads();

    for (int kt = 0; kt < EMB / 32; kt++) {
        if (kt + 1 < EMB / 32) {
            GLOAD(kt + 1, (kt + 1) & 1);
            cp_commit();
        }

        const __half* As = Asm + (kt & 1) * 128 * ASTR;
        const __half* Bs = Bsm + (kt & 1) * 128 * BSTR;
#pragma unroll
        for (int ks = 0; ks < 2; ks++) {
            int k0 = ks * 16;
            unsigned af[4][4], bf[4][2];
            // A frags: matrices (row+0,k+0),(row+8,k+0),(row+0,k+8),(row+8,k+8)
#pragma unroll
            for (int mt = 0; mt < 4; mt++) {
                uint32_t addr = sa(As + (wm + mt * 16 + ((lmat & 1) << 3) + lrow) * ASTR
                                   + k0 + ((lmat >> 1) << 3));
                LDSM4(af[mt][0], af[mt][1], af[mt][2], af[mt][3], addr);
            }
            // B frags: per nt-pair p: (n+0,k+0),(n+0,k+8),(n+8,k+0),(n+8,k+8)
#pragma unroll
            for (int p = 0; p < 2; p++) {
                uint32_t addr = sa(Bs + (wn + p * 16 + ((lmat >> 1) << 3) + lrow) * BSTR
                                   + k0 + ((lmat & 1) << 3));
                LDSM4(bf[2*p][0], bf[2*p][1], bf[2*p+1][0], bf[2*p+1][1], addr);
            }
#pragma unroll
            for (int mt = 0; mt < 4; mt++)
#pragma unroll
                for (int nt = 0; nt < 4; nt++)
                    mma_f16(acc[mt][nt], af[mt], bf[nt]);
        }
        if (kt + 1 < EMB / 32) {
            cp_wait0();
            __syncthreads();
        }
    }

    float os = ga.oscale[z];
#pragma unroll
    for (int mt = 0; mt < 4; mt++)
#pragma unroll
        for (int nt = 0; nt < 4; nt++) {
            int gm = bm + wm + mt * 16 + gid;
            int gn = bn + wn + nt * 8 + tig * 2;
            float b0 = bias[gn], b1 = bias[gn + 1];
            float v0 = (acc[mt][nt][0] + b0) * os;
            float v1 = (acc[mt][nt][1] + b1) * os;
            float v2 = (acc[mt][nt][2] + b0) * os;
            float v3 = (acc[mt][nt][3] + b1) * os;
            if (ga.half_out) {
                __half* C = (__half*)ga.out[z];
                *(__half2*)(C + (long)gm * EMB + gn) = __floats2half2_rn(v0, v1);
                *(__half2*)(C + (long)(gm + 8) * EMB + gn) = __floats2half2_rn(v2, v3);
            } else {
                float* C = (float*)ga.out[z];
                *(float2*)(C + (long)gm * EMB + gn) = make_float2(v0, v1);
                *(float2*)(C + (long)(gm + 8) * EMB + gn) = make_float2(v2, v3);
            }
        }
}

// ---------------- FP16 flash attention (ldmatrix, shuffle-free PV) ----------
#define BQ 128
#define BKV 64
#define QSTR 72   // halves; 144B rows -> ldmatrix conflict-free
#define KSTR 72
#define VSTR 72

__global__ __launch_bounds__(256, 2) void flash_f16(
    const __half* __restrict__ Q, const __half* __restrict__ K,
    const __half* __restrict__ Vt, const int* __restrict__ mask,
    const int* __restrict__ msum, __half* __restrict__ ctx)
{
    extern __shared__ __half fsm[];
    __half* Qs = fsm;                         // BQ*QSTR
    __half* Ks = Qs + BQ * QSTR;              // 2*BKV*KSTR  (rows = s)
    __half* Vs = Ks + 2 * BKV * KSTR;         // 2*HD*VSTR   (rows = d)

    int tid = threadIdx.x;
    int w = tid / 32, lane = tid % 32;
    int gid = lane >> 2, tig = lane & 3;
    int lrow = lane & 7, lmat = lane >> 3;
    int qt = blockIdx.x, h = blockIdx.y, b = blockIdx.z;
    int q0 = qt * BQ;
    int bh = b * NH + h;

    // Q tile: 128 rows x 64 halves (128B/row)
    {
        int row = tid >> 1;
        int c0 = (tid & 1) * 32;
        const __half* g = Q + (long)(b * SEQ + q0 + row) * EMB + h * HD + c0;
        uint32_t s = sa(Qs + row * QSTR + c0);
#pragma unroll
        for (int j = 0; j < 4; j++) cpa16(s + j * 16, g + j * 8);
    }
    // K / Vt tile 0: 64 rows x 64 halves each
    {
        int row = tid >> 2;
        int c0 = (tid & 3) * 16;
        const __half* kg = K + (long)(b * SEQ + row) * EMB + h * HD + c0;
        uint32_t ksm = sa(Ks + row * KSTR + c0);
        cpa16(ksm, kg); cpa16(ksm + 16, kg + 8);
        const __half* vg = Vt + ((long)bh * HD + row) * SEQ + c0;
        uint32_t vsm = sa(Vs + row * VSTR + c0);
        cpa16(vsm, vg); cpa16(vsm + 16, vg + 8);
    }
    cp_commit();
    cp_wait0();
    __syncthreads();

    // hoist Q fragments: 4 k16-steps
    unsigned aq[4][4];
#pragma unroll
    for (int ks = 0; ks < 4; ks++) {
        uint32_t addr = sa(Qs + (w * 16 + ((lmat & 1) << 3) + lrow) * QSTR
                           + ks * 16 + ((lmat >> 1) << 3));
        LDSM4(aq[ks][0], aq[ks][1], aq[ks][2], aq[ks][3], addr);
    }

    float o[8][4];
#pragma unroll
    for (int dt = 0; dt < 8; dt++)
#pragma unroll
        for (int r = 0; r < 4; r++) o[dt][r] = 0.0f;
    float mA = -1e30f, mB = -1e30f, lA = 0.0f, lB = 0.0f;

    for (int kt = 0; kt < NKT; kt++) {
        if (kt + 1 < NKT) {
            int nb = (kt + 1) & 1;
            int row = tid >> 2;
            int c0 = (tid & 3) * 16;
            const __half* kg = K + (long)(b * SEQ + (kt + 1) * BKV + row) * EMB + h * HD + c0;
            uint32_t ksm = sa(Ks + nb * BKV * KSTR + row * KSTR + c0);
            cpa16(ksm, kg); cpa16(ksm + 16, kg + 8);
            const __half* vg = Vt + ((long)bh * HD + row) * SEQ + (kt + 1) * BKV + c0;
            uint32_t vsm = sa(Vs + nb * HD * VSTR + row * VSTR + c0);
            cpa16(vsm, vg); cpa16(vsm + 16, vg + 8);
            cp_commit();
        }

        const __half* Kb = Ks + (kt & 1) * BKV * KSTR;
        const __half* Vb = Vs + (kt & 1) * HD * VSTR;

        // S = Q K^T  (B frags: rows = s, content = d)
        float s[8][4];
#pragma unroll
        for (int nt = 0; nt < 8; nt++)
#pragma unroll
            for (int r = 0; r < 4; r++) s[nt][r] = 0.0f;
#pragma unroll
        for (int ks = 0; ks < 4; ks++) {
            int k0 = ks * 16;
            unsigned bk[8][2];
#pragma unroll
            for (int p = 0; p < 4; p++) {
                uint32_t addr = sa(Kb + (p * 16 + ((lmat >> 1) << 3) + lrow) * KSTR
                                   + k0 + ((lmat & 1) << 3));
                LDSM4(bk[2*p][0], bk[2*p][1], bk[2*p+1][0], bk[2*p+1][1], addr);
            }
#pragma unroll
            for (int nt = 0; nt < 8; nt++)
                mma_f16(s[nt], aq[ks], bk[nt]);
        }

        // mask (only when tile contains zeros)
        if (!msum[qt * NKT + kt]) {
            int qrA = q0 + w * 16 + gid;
            int qrB = qrA + 8;
#pragma unroll
            for (int nt = 0; nt < 8; nt++) {
                int kc = kt * 64 + nt * 8 + tig * 2;
                const int* mpA = mask + (long)qrA * SEQ + kc;
                const int* mpB = mask + (long)qrB * SEQ + kc;
                if (mpA[0] == 0) s[nt][0] = -1e30f;
                if (mpA[1] == 0) s[nt][1] = -1e30f;
                if (mpB[0] == 0) s[nt][2] = -1e30f;
                if (mpB[1] == 0) s[nt][3] = -1e30f;
            }
        }

        // online softmax (rows gid / gid+8)
        float mxA = -1e30f, mxB = -1e30f;
#pragma unroll
        for (int nt = 0; nt < 8; nt++) {
            mxA = fmaxf(mxA, fmaxf(s[nt][0], s[nt][1]));
            mxB = fmaxf(mxB, fmaxf(s[nt][2], s[nt][3]));
        }
#pragma unroll
        for (int off = 1; off < 4; off <<= 1) {
            mxA = fmaxf(mxA, __shfl_xor_sync(0xffffffffu, mxA, off));
            mxB = fmaxf(mxB, __shfl_xor_sync(0xffffffffu, mxB, off));
        }
        float mnA = fmaxf(mA, mxA), mnB = fmaxf(mB, mxB);
        float fA = __expf(mA - mnA), fB = __expf(mB - mnB);
        mA = mnA; mB = mnB;
        float sumA = 0.0f, sumB = 0.0f;
#pragma unroll
        for (int nt = 0; nt < 8; nt++) {
            s[nt][0] = __expf(s[nt][0] - mA);
            s[nt][1] = __expf(s[nt][1] - mA);
            s[nt][2] = __expf(s[nt][2] - mB);
            s[nt][3] = __expf(s[nt][3] - mB);
            sumA += s[nt][0] + s[nt][1];
            sumB += s[nt][2] + s[nt][3];
        }
#pragma unroll
        for (int off = 1; off < 4; off <<= 1) {
            sumA += __shfl_xor_sync(0xffffffffu, sumA, off);
            sumB += __shfl_xor_sync(0xffffffffu, sumB, off);
        }
        lA = lA * fA + sumA;
        lB = lB * fB + sumB;
#pragma unroll
        for (int dt = 0; dt < 8; dt++) {
            o[dt][0] *= fA; o[dt][1] *= fA;
            o[dt][2] *= fB; o[dt][3] *= fB;
        }

        // O += P V : fp16 A-frag == C-frag layout -> direct pack, no shuffles
#pragma unroll
        for (int ks = 0; ks < 4; ks++) {
            unsigned pa[4];
            pa[0] = h2u(__floats2half2_rn(s[2*ks][0],   s[2*ks][1]));
            pa[1] = h2u(__floats2half2_rn(s[2*ks][2],   s[2*ks][3]));
            pa[2] = h2u(__floats2half2_rn(s[2*ks+1][0], s[2*ks+1][1]));
            pa[3] = h2u(__floats2half2_rn(s[2*ks+1][2], s[2*ks+1][3]));
            int k0 = ks * 16;
            unsigned bv[8][2];
#pragma unroll
            for (int p = 0; p < 4; p++) {
                uint32_t addr = sa(Vb + (p * 16 + ((lmat >> 1) << 3) + lrow) * VSTR
                                   + k0 + ((lmat & 1) << 3));
                LDSM4(bv[2*p][0], bv[2*p][1], bv[2*p+1][0], bv[2*p+1][1], addr);
            }
#pragma unroll
            for (int dt = 0; dt < 8; dt++)
                mma_f16(o[dt], pa, bv[dt]);
        }

        if (kt + 1 < NKT) {
            cp_wait0();
            __syncthreads();
        }
    }

    // finalize -> ctx fp16
    float invA = 1.0f / lA, invB = 1.0f / lB;
    long rowA = (long)(b * SEQ + q0 + w * 16 + gid) * EMB;
    long rowB = rowA + 8L * EMB;
#pragma unroll
    for (int dt = 0; dt < 8; dt++) {
        int gn = h * HD + dt * 8 + tig * 2;
        *(__half2*)(ctx + rowA + gn) = __floats2half2_rn(o[dt][0] * invA, o[dt][1] * invA);
        *(__half2*)(ctx + rowB + gn) = __floats2half2_rn(o[dt][2] * invB, o[dt][3] * invB);
    }
}

// ---------------- launch ----------------------------------------------------
extern "C" void kernel_launch(void* const* d_in, const int* in_sizes, int n_in,
                              void* d_out, int out_size)
{
    const float* x    = (const float*)d_in[0];
    const int*   mask = (const int*)  d_in[1];
    const float* Wq   = (const float*)d_in[2];
    const float* bq   = (const float*)d_in[3];
    const float* Wk   = (const float*)d_in[4];
    const float* bk   = (const float*)d_in[5];
    const float* Wv   = (const float*)d_in[6];
    const float* bv   = (const float*)d_in[7];
    const float* Wo   = (const float*)d_in[8];
    const float* bo   = (const float*)d_in[9];
    float* out = (float*)d_out;

    __half *pWq, *pWk, *pWv, *pWo, *pXr, *pQ, *pK, *pV, *pVt, *pCtx;
    int* pMsum;
    cudaGetSymbolAddress((void**)&pWq, g_Wq);
    cudaGetSymbolAddress((void**)&pWk, g_Wk);
    cudaGetSymbolAddress((void**)&pWv, g_Wv);
    cudaGetSymbolAddress((void**)&pWo, g_Wo);
    cudaGetSymbolAddress((void**)&pXr, g_xr);
    cudaGetSymbolAddress((void**)&pQ,  g_Q);
    cudaGetSymbolAddress((void**)&pK,  g_K);
    cudaGetSymbolAddress((void**)&pV,  g_V);
    cudaGetSymbolAddress((void**)&pVt, g_Vt);
    cudaGetSymbolAddress((void**)&pCtx, g_ctx);
    cudaGetSymbolAddress((void**)&pMsum, g_msum);

    const int gemm_smem  = (2*128*ASTR + 2*128*BSTR) * (int)sizeof(__half);          // 40KB
    const int flash_smem = (BQ*QSTR + 2*BKV*KSTR + 2*HD*VSTR) * (int)sizeof(__half); // ~54KB
    cudaFuncSetAttribute(gemm_f16, cudaFuncAttributeMaxDynamicSharedMemorySize, gemm_smem);
    cudaFuncSetAttribute(flash_f16, cudaFuncAttributeMaxDynamicSharedMemorySize, flash_smem);

    // 1. prolog
    Exp4 e;
    e.W[0] = Wq; e.W[1] = Wk; e.W[2] = Wv; e.W[3] = Wo;
    e.Wb[0] = pWq; e.Wb[1] = pWk; e.Wb[2] = pWv; e.Wb[3] = pWo;
    expand4_kernel<<<dim3(NBQ*NBQ/256, 4), 256>>>(e);
    round_kernel<<<(NROWS*EMB/4 + 255)/256, 256>>>(x, pXr, NROWS*EMB/4);
    mask_summary<<<NQT*NKT, 256>>>(mask, pMsum);

    // 2. fused Q/K/V projections (Q prescaled by 1/8; all fp16 outputs)
    GemmArgs qkv;
    qkv.A = pXr;
    qkv.W[0] = pWq; qkv.W[1] = pWk; qkv.W[2] = pWv;
    qkv.bias[0] = bq; qkv.bias[1] = bk; qkv.bias[2] = bv;
    qkv.out[0] = pQ; qkv.out[1] = pK; qkv.out[2] = pV;
    qkv.oscale[0] = 0.125f; qkv.oscale[1] = 1.0f; qkv.oscale[2] = 1.0f;
    qkv.half_out = 1;
    dim3 ggrid(EMB/128, NROWS/128, 3);
    gemm_f16<<<ggrid, 256, gemm_smem>>>(qkv);

    // 2b. transpose V -> [b,h,d,s]
    vtrans_kernel<<<dim3(SEQ/64, NBATCH*NH), 256>>>(pV, pVt);

    // 3. attention
    dim3 agrid(SEQ/BQ, NH, NBATCH);
    flash_f16<<<agrid, 256, flash_smem>>>(pQ, pK, pVt, mask, pMsum, pCtx);

    // 4. output projection -> d_out (fp32)
    GemmArgs og;
    og.A = pCtx;
    og.W[0] = pWo; og.W[1] = pWo; og.W[2] = pWo;
    og.bias[0] = bo; og.bias[1] = bo; og.bias[2] = bo;
    og.out[0] = out; og.out[1] = out; og.out[2] = out;
    og.oscale[0] = 1.0f; og.oscale[1] = 1.0f; og.oscale[2] = 1.0f;
    og.half_out = 0;
    dim3 ogrid(EMB/128, NROWS/128, 1);
    gemm_f16<<<ogrid, 256, gemm_smem>>>(og);
}